// round 1
// baseline (speedup 1.0000x reference)
#include <cuda_runtime.h>
#include <cuda_bf16.h>
#include <cstdint>

// Problem constants (fixed by setup_inputs)
#define M_TOT 16384   // 8 * 2048
#define N_TOT 4096    // out_features
#define K_TOT 4096    // in_features
#define BXQ 4
#define BYQ 4
#define NCQ 256
#define BSQ 8
#define OUT_DIM 1024  // N_TOT / BXQ
#define IN_DIM  1024  // K_TOT / BYQ
#define NUM_BLK 128   // IN_DIM / BSQ
#define JDIM (NUM_BLK * OUT_DIM)  // 131072

// Scratch: reconstructed weight, row-major [N_TOT, K_TOT]
__device__ float g_W[(size_t)N_TOT * K_TOT];

// ---------------------------------------------------------------------------
// Kernel 1: reconstruct W from centroids/assignments.
// W[bx*1024 + od, by*1024 + nb*8 + s] = centroids[bx, by, assignments[bx,by, nb*1024+od], s]
// ---------------------------------------------------------------------------
__global__ void reconstruct_kernel(const float* __restrict__ centroids,
                                   const int* __restrict__ assignments) {
    int idx = blockIdx.x * blockDim.x + threadIdx.x;
    if (idx >= BXQ * BYQ * JDIM) return;
    int j  = idx % JDIM;
    int by = (idx / JDIM) % BYQ;
    int bx = idx / (JDIM * BYQ);
    int nb = j / OUT_DIM;
    int od = j % OUT_DIM;
    int a  = assignments[idx];

    const float4* c = reinterpret_cast<const float4*>(
        centroids + ((((size_t)bx * BYQ + by) * NCQ + a) * BSQ));
    size_t o = (size_t)bx * OUT_DIM + od;
    size_t i = (size_t)by * IN_DIM + (size_t)nb * BSQ;
    float4* w = reinterpret_cast<float4*>(g_W + o * K_TOT + i);
    w[0] = c[0];
    w[1] = c[1];
}

// ---------------------------------------------------------------------------
// Kernel 2: SGEMM  C[m, n] = sum_k A[m,k] * W[n,k] + bias[n]
// A: [M_TOT, K_TOT] row-major (x flattened), W: [N_TOT, K_TOT] row-major.
// 128x128 block tile, K-tile 16, 256 threads, 8x8 per-thread micro-tile.
// ---------------------------------------------------------------------------
#define BM 128
#define BN 128
#define BK 16
#define SMEM_LD 132   // padded to kill store bank conflicts

__global__ __launch_bounds__(256, 2)
void sgemm_kernel(const float* __restrict__ A,
                  const float* __restrict__ bias,
                  float* __restrict__ C) {
    __shared__ float As[BK][SMEM_LD];
    __shared__ float Bs[BK][SMEM_LD];

    const float* __restrict__ B = g_W;

    const int tid = threadIdx.x;
    const int m0 = blockIdx.y * BM;
    const int n0 = blockIdx.x * BN;

    const int tx = tid & 15;   // 0..15 -> N direction
    const int ty = tid >> 4;   // 0..15 -> M direction

    float acc[8][8];
#pragma unroll
    for (int i = 0; i < 8; i++)
#pragma unroll
        for (int j = 0; j < 8; j++) acc[i][j] = 0.f;

    // global tile load mapping: 256 threads, each loads 2 float4 from A and B
    const int lrow = tid >> 2;         // 0..63
    const int lcol = (tid & 3) << 2;   // 0,4,8,12

    const float* Aptr = A + (size_t)(m0 + lrow) * K_TOT + lcol;
    const float* Bptr = B + (size_t)(n0 + lrow) * K_TOT + lcol;

    for (int k0 = 0; k0 < K_TOT; k0 += BK) {
#pragma unroll
        for (int r = 0; r < 2; r++) {
            float4 va = *reinterpret_cast<const float4*>(Aptr + (size_t)r * 64 * K_TOT + k0);
            As[lcol + 0][lrow + r * 64] = va.x;
            As[lcol + 1][lrow + r * 64] = va.y;
            As[lcol + 2][lrow + r * 64] = va.z;
            As[lcol + 3][lrow + r * 64] = va.w;
            float4 vb = *reinterpret_cast<const float4*>(Bptr + (size_t)r * 64 * K_TOT + k0);
            Bs[lcol + 0][lrow + r * 64] = vb.x;
            Bs[lcol + 1][lrow + r * 64] = vb.y;
            Bs[lcol + 2][lrow + r * 64] = vb.z;
            Bs[lcol + 3][lrow + r * 64] = vb.w;
        }
        __syncthreads();

#pragma unroll
        for (int k = 0; k < BK; k++) {
            float ra[8], rb[8];
#pragma unroll
            for (int i = 0; i < 8; i++) ra[i] = As[k][ty * 8 + i];
#pragma unroll
            for (int j = 0; j < 8; j++) rb[j] = Bs[k][tx * 8 + j];
#pragma unroll
            for (int i = 0; i < 8; i++)
#pragma unroll
                for (int j = 0; j < 8; j++)
                    acc[i][j] += ra[i] * rb[j];
        }
        __syncthreads();
    }

    // epilogue: add bias and store (vectorized)
    float rbias[8];
#pragma unroll
    for (int j = 0; j < 8; j++) rbias[j] = bias[n0 + tx * 8 + j];

#pragma unroll
    for (int i = 0; i < 8; i++) {
        size_t row = (size_t)(m0 + ty * 8 + i);
        float* cp = C + row * N_TOT + n0 + tx * 8;
        float4 o0, o1;
        o0.x = acc[i][0] + rbias[0];
        o0.y = acc[i][1] + rbias[1];
        o0.z = acc[i][2] + rbias[2];
        o0.w = acc[i][3] + rbias[3];
        o1.x = acc[i][4] + rbias[4];
        o1.y = acc[i][5] + rbias[5];
        o1.z = acc[i][6] + rbias[6];
        o1.w = acc[i][7] + rbias[7];
        reinterpret_cast<float4*>(cp)[0] = o0;
        reinterpret_cast<float4*>(cp)[1] = o1;
    }
}

// ---------------------------------------------------------------------------
// kernel_launch: inputs in metadata order:
//   0: x           float32  [8,2048,4096]
//   1: centroids   float32  [4,4,256,8]
//   2: bias        float32  [4096]
//   3: assignments int32    [4,4,131072]
//   4: sample_in_dim  int32 [1]  (== 4096, full)
//   5: sample_out_dim int32 [1]  (== 4096, full)
// output: float32 [8,2048,4096]
// ---------------------------------------------------------------------------
extern "C" void kernel_launch(void* const* d_in, const int* in_sizes, int n_in,
                              void* d_out, int out_size) {
    const float* x           = (const float*)d_in[0];
    const float* centroids   = (const float*)d_in[1];
    const float* bias        = (const float*)d_in[2];
    const int*   assignments = (const int*)d_in[3];
    float* out = (float*)d_out;

    // 1) reconstruct weight into g_W
    {
        int total = BXQ * BYQ * JDIM;   // 2,097,152
        int threads = 256;
        int blocks = (total + threads - 1) / threads;
        reconstruct_kernel<<<blocks, threads>>>(centroids, assignments);
    }

    // 2) GEMM + bias
    {
        dim3 grid(N_TOT / BN, M_TOT / BM);  // (32, 128)
        sgemm_kernel<<<grid, 256>>>(x, bias, out);
    }
}

// round 3
// speedup vs baseline: 8.9284x; 8.9284x over previous
#include <cuda_runtime.h>
#include <cuda_fp16.h>
#include <cstdint>

// ---------------------------------------------------------------------------
// Problem constants
// ---------------------------------------------------------------------------
#define M_TOT 16384   // 8 * 2048
#define N_TOT 4096
#define K_TOT 4096
#define BXQ 4
#define BYQ 4
#define NCQ 256
#define BSQ 8
#define OUT_DIM 1024
#define IN_DIM  1024
#define NUM_BLK 128
#define JDIM (NUM_BLK * OUT_DIM)  // 131072

// GEMM tiling
#define BM 128
#define BN 128
#define BK 64
#define KT_STEPS (K_TOT / BK)     // 64
#define STAGES 3

// SMEM stage layout: A tile 128x64 fp16 (16KB, SW128) then B tile (16KB)
#define ST_A 0
#define ST_B (16 * 1024)
#define STAGE_SZ (32 * 1024)
#define SMEM_DYN (STAGES * STAGE_SZ)   // 96 KB

// ---------------------------------------------------------------------------
// Scratch (device globals; allocation-free rule)
// ---------------------------------------------------------------------------
__device__ __half g_A[(size_t)M_TOT * K_TOT];   // x as fp16, row-major [M,K]
__device__ __half g_W[(size_t)N_TOT * K_TOT];   // reconstructed W fp16 [N,K]

// ---------------------------------------------------------------------------
// Helpers
// ---------------------------------------------------------------------------
__device__ __forceinline__ uint32_t smem_u32(const void* p) {
    uint32_t a;
    asm("{ .reg .u64 t; cvta.to.shared.u64 t, %1; cvt.u32.u64 %0, t; }" : "=r"(a) : "l"(p));
    return a;
}
__device__ __forceinline__ void cp16(uint32_t saddr, const void* gaddr) {
    asm volatile("cp.async.cg.shared.global [%0], [%1], 16;" :: "r"(saddr), "l"(gaddr) : "memory");
}
__device__ __forceinline__ void ldsm_x4(uint32_t addr, uint32_t& r0, uint32_t& r1,
                                        uint32_t& r2, uint32_t& r3) {
    asm volatile("ldmatrix.sync.aligned.m8n8.x4.shared.b16 {%0,%1,%2,%3}, [%4];"
                 : "=r"(r0), "=r"(r1), "=r"(r2), "=r"(r3) : "r"(addr));
}
__device__ __forceinline__ void mma16816(float* c, const uint32_t* a, const uint32_t* b) {
    asm volatile("mma.sync.aligned.m16n8k16.row.col.f32.f16.f16.f32 "
                 "{%0,%1,%2,%3}, {%4,%5,%6,%7}, {%8,%9}, {%0,%1,%2,%3};"
                 : "+f"(c[0]), "+f"(c[1]), "+f"(c[2]), "+f"(c[3])
                 : "r"(a[0]), "r"(a[1]), "r"(a[2]), "r"(a[3]), "r"(b[0]), "r"(b[1]));
}

// ---------------------------------------------------------------------------
// Prep kernel 1: x (fp32) -> fp16
// ---------------------------------------------------------------------------
__global__ void convert_x_kernel(const float4* __restrict__ x) {
    size_t i = (size_t)blockIdx.x * blockDim.x + threadIdx.x;  // float4 index
    float4 v = x[i];
    __half2* p = reinterpret_cast<__half2*>(g_A) + 2 * i;
    p[0] = __halves2half2(__float2half_rn(v.x), __float2half_rn(v.y));
    p[1] = __halves2half2(__float2half_rn(v.z), __float2half_rn(v.w));
}

// ---------------------------------------------------------------------------
// Prep kernel 2: reconstruct W from PQ codebook -> fp16
// ---------------------------------------------------------------------------
__global__ void reconstruct_kernel(const float* __restrict__ centroids,
                                   const int* __restrict__ assignments) {
    int idx = blockIdx.x * blockDim.x + threadIdx.x;
    int j  = idx % JDIM;
    int by = (idx / JDIM) % BYQ;
    int bx = idx / (JDIM * BYQ);
    int nb = j / OUT_DIM;
    int od = j % OUT_DIM;
    int a  = assignments[idx];

    const float4* c = reinterpret_cast<const float4*>(
        centroids + ((((size_t)bx * BYQ + by) * NCQ + a) * BSQ));
    float4 c0 = c[0], c1 = c[1];

    size_t o  = (size_t)bx * OUT_DIM + od;
    size_t ii = (size_t)by * IN_DIM + (size_t)nb * BSQ;
    __half2 h[4];
    h[0] = __halves2half2(__float2half_rn(c0.x), __float2half_rn(c0.y));
    h[1] = __halves2half2(__float2half_rn(c0.z), __float2half_rn(c0.w));
    h[2] = __halves2half2(__float2half_rn(c1.x), __float2half_rn(c1.y));
    h[3] = __halves2half2(__float2half_rn(c1.z), __float2half_rn(c1.w));
    *reinterpret_cast<uint4*>(g_W + o * K_TOT + ii) = *reinterpret_cast<uint4*>(h);
}

// ---------------------------------------------------------------------------
// GEMM: C[m,n] = sum_k A[m,k]*W[n,k] + bias[n]   (fp16 HMMA, fp32 accum)
// 128x128x64 CTA tile, 8 warps (2x4), warp tile 64x32, 3-stage cp.async.
// ---------------------------------------------------------------------------
__device__ __forceinline__ void load_stage(uint32_t sb, int buf, int kt,
                                           int m0, int n0, int tid) {
    const uint32_t stg = sb + (uint32_t)buf * STAGE_SZ;
    const int kofs = kt * BK;
    // A: 128 rows x 8 chunks(16B) = 1024 chunks; B same. 4 each per thread.
#pragma unroll
    for (int j = 0; j < 4; j++) {
        int i = tid + 256 * j;
        int row = i >> 3, ch = i & 7;
        uint32_t soff = (uint32_t)(row * 128) + (uint32_t)((ch ^ (row & 7)) << 4);
        cp16(stg + ST_A + soff, g_A + (size_t)(m0 + row) * K_TOT + kofs + ch * 8);
        cp16(stg + ST_B + soff, g_W + (size_t)(n0 + row) * K_TOT + kofs + ch * 8);
    }
    asm volatile("cp.async.commit_group;" ::: "memory");
}

__global__ __launch_bounds__(256, 2)
void hgemm_kernel(const float* __restrict__ bias, float* __restrict__ C) {
    extern __shared__ char smem_raw[];
    const uint32_t sb = smem_u32(smem_raw);

    const int tid = threadIdx.x;
    const int wid = tid >> 5;
    const int lane = tid & 31;
    const int warp_m = wid >> 2;     // 0..1
    const int warp_n = wid & 3;      // 0..3
    const int m0 = blockIdx.y * BM;
    const int n0 = blockIdx.x * BN;

    float acc[4][4][4];
#pragma unroll
    for (int i = 0; i < 4; i++)
#pragma unroll
        for (int j = 0; j < 4; j++)
#pragma unroll
            for (int e = 0; e < 4; e++) acc[i][j][e] = 0.f;

    // prologue
    load_stage(sb, 0, 0, m0, n0, tid);
    load_stage(sb, 1, 1, m0, n0, tid);

    // precomputed ldmatrix lane addressing
    const int a_row = warp_m * 64 + (lane & 15);       // + mf*16
    const int a_csel = lane >> 4;                      // k 16B-chunk parity
    const int b_row = warp_n * 32 + (lane & 7) + ((lane & 16) >> 1);  // + bp*16
    const int b_csel = (lane & 8) >> 3;

    for (int kt = 0; kt < KT_STEPS; kt++) {
        if (kt + 2 < KT_STEPS) asm volatile("cp.async.wait_group 1;" ::: "memory");
        else                   asm volatile("cp.async.wait_group 0;" ::: "memory");
        __syncthreads();

        if (kt + 2 < KT_STEPS)
            load_stage(sb, (kt + 2) % STAGES, kt + 2, m0, n0, tid);

        const uint32_t stg = sb + (uint32_t)(kt % STAGES) * STAGE_SZ;
#pragma unroll
        for (int s = 0; s < 4; s++) {
            uint32_t a[4][4], b[4][2];
            const int ac = s * 2 + a_csel;
            const int bc = s * 2 + b_csel;
#pragma unroll
            for (int mf = 0; mf < 4; mf++) {
                int row = a_row + mf * 16;
                uint32_t addr = stg + ST_A + row * 128 + ((ac ^ (row & 7)) << 4);
                ldsm_x4(addr, a[mf][0], a[mf][1], a[mf][2], a[mf][3]);
            }
#pragma unroll
            for (int bp = 0; bp < 2; bp++) {
                int row = b_row + bp * 16;
                uint32_t addr = stg + ST_B + row * 128 + ((bc ^ (row & 7)) << 4);
                ldsm_x4(addr, b[2 * bp][0], b[2 * bp][1], b[2 * bp + 1][0], b[2 * bp + 1][1]);
            }
#pragma unroll
            for (int mf = 0; mf < 4; mf++)
#pragma unroll
                for (int nf = 0; nf < 4; nf++)
                    mma16816(acc[mf][nf], a[mf], b[nf]);
        }
        __syncthreads();
    }

    // epilogue: bias add + store fp32
#pragma unroll
    for (int nf = 0; nf < 4; nf++) {
        const int col = n0 + warp_n * 32 + nf * 8 + (lane & 3) * 2;
        const float b0 = bias[col];
        const float b1 = bias[col + 1];
#pragma unroll
        for (int mf = 0; mf < 4; mf++) {
            const int row = m0 + warp_m * 64 + mf * 16 + (lane >> 2);
            float2 v0 = make_float2(acc[mf][nf][0] + b0, acc[mf][nf][1] + b1);
            float2 v1 = make_float2(acc[mf][nf][2] + b0, acc[mf][nf][3] + b1);
            *reinterpret_cast<float2*>(C + (size_t)row * N_TOT + col) = v0;
            *reinterpret_cast<float2*>(C + (size_t)(row + 8) * N_TOT + col) = v1;
        }
    }
}

// ---------------------------------------------------------------------------
// kernel_launch
//   0: x f32 [8,2048,4096]  1: centroids f32 [4,4,256,8]  2: bias f32 [4096]
//   3: assignments i32 [4,4,131072]  4/5: sample dims (full 4096)
// ---------------------------------------------------------------------------
extern "C" void kernel_launch(void* const* d_in, const int* in_sizes, int n_in,
                              void* d_out, int out_size) {
    const float* x           = (const float*)d_in[0];
    const float* centroids   = (const float*)d_in[1];
    const float* bias        = (const float*)d_in[2];
    const int*   assignments = (const int*)d_in[3];
    float* out = (float*)d_out;

    cudaFuncSetAttribute(hgemm_kernel,
                         cudaFuncAttributeMaxDynamicSharedMemorySize, SMEM_DYN);

    // 1) x -> fp16   (16,777,216 float4s)
    convert_x_kernel<<<65536, 256>>>(reinterpret_cast<const float4*>(x));

    // 2) reconstruct W -> fp16   (2,097,152 code blocks)
    reconstruct_kernel<<<8192, 256>>>(centroids, assignments);

    // 3) tensor-core GEMM + bias
    dim3 grid(N_TOT / BN, M_TOT / BM);   // (32, 128)
    hgemm_kernel<<<grid, 256, SMEM_DYN>>>(bias, out);
}